// round 13
// baseline (speedup 1.0000x reference)
#include <cuda_runtime.h>
#include <cuda_bf16.h>
#include <cuda_fp16.h>
#include <cstdint>
#include <cstddef>

// ---------------- problem constants ----------------
#define SQ   32
#define PP64 64
#define NB   2048
#define PPRW 4096
#define D1   512
#define D2   1024
#define NKAP 16
#define EPSV 1e-5f

// ---------------- scratch ----------------
__device__ __align__(256) float g_a  [NB * 512];
__device__ __align__(256) float g_hW [NB * 512];
__device__ __align__(256) float g_U  [NB * NKAP * 512];
__device__ __align__(256) float g_V  [NKAP * 512];
__device__ float  g_sum1[SQ * 512];
__device__ float  g_sq1 [SQ * 512];
__device__ float2 g_ab1 [SQ * 512];
__device__ float  g_sum2[SQ * D2];
__device__ float  g_sq2 [SQ * D2];
__device__ float2 g_ab2 [SQ * D2];
__device__ __align__(256) float g_maxZ[NB * D2];
__device__ __align__(256) float g_minZ[NB * D2];
// fp16 operands for HMMA GEMM2
__device__ __align__(256) __half g_Ah[(size_t)NB * PP64 * 512];   // 134 MB
__device__ __align__(256) __half g_Bh[(size_t)D2 * 512];          // W2^T fp16

__device__ __forceinline__ uint32_t smem_u32(const void* p) {
    uint32_t a;
    asm("{ .reg .u64 t; cvta.to.shared.u64 t, %1; cvt.u32.u64 %0, t; }" : "=r"(a) : "l"(p));
    return a;
}

// ---------------- K0: zero BN accumulators ----------------
__global__ void k_zero() {
    int i = blockIdx.x * blockDim.x + threadIdx.x;
    if (i < SQ * 512) { g_sum1[i] = 0.f; g_sq1[i] = 0.f; }
    if (i < SQ * D2)  { g_sum2[i] = 0.f; g_sq2[i] = 0.f; }
}

// ---------------- K1: a = obs @ W_sp ; hW = h @ W1[512:576,:] ----------------
__global__ void k_embed(const float* __restrict__ traj, const float* __restrict__ Wsp,
                        const float* __restrict__ hs,   const float* __restrict__ W1) {
    int b = blockIdx.x;
    int tid = threadIdx.x;
    __shared__ float obs[16];
    __shared__ float hsh[64];
    if (tid < 16) {
        int t = tid >> 1, c = tid & 1;
        obs[tid] = traj[((size_t)t * NB + b) * 2 + c];
    }
    if (tid < 64) hsh[tid] = hs[b * 64 + tid];
    __syncthreads();
#pragma unroll
    for (int q = 0; q < 4; q++) {
        int f = tid + 128 * q;
        float acc = 0.f;
#pragma unroll
        for (int r = 0; r < 16; r++) acc = fmaf(obs[r], Wsp[r * 512 + f], acc);
        g_a[b * 512 + f] = acc;
        float ah = 0.f;
#pragma unroll
        for (int k = 0; k < 64; k++) ah = fmaf(hsh[k], W1[(512 + k) * 512 + f], ah);
        g_hW[b * 512 + f] = ah;
    }
}

// ---------------- K1b: V[kap][d] ----------------
__global__ void k_V(const float* __restrict__ bsp, const float* __restrict__ W1) {
    int d = blockIdx.x * 128 + threadIdx.x;
#pragma unroll
    for (int kap = 0; kap < NKAP; kap++) {
        int par = kap >> 3, t = kap & 7;
        float acc = 0.f;
#pragma unroll 4
        for (int e = par; e < 64; e += 2) {
            int f = t * 64 + e;
            acc = fmaf(bsp[f], W1[f * 512 + d], acc);
        }
        g_V[kap * 512 + d] = acc;
    }
}

// ---------------- K2: U[b][kap][d]; 16 peds/block, kappa split x2 ----------------
__global__ void k_U(const float* __restrict__ W1) {
    int b0 = blockIdx.x * 16;
    int kap0 = blockIdx.y * 8;
    int d  = threadIdx.x;
    __shared__ float a[16][512];
    for (int idx = threadIdx.x; idx < 16 * 512; idx += 512)
        a[idx >> 9][idx & 511] = g_a[b0 * 512 + idx];
    __syncthreads();
#pragma unroll 1
    for (int kk = 0; kk < 8; kk++) {
        int kap = kap0 + kk;
        int par = kap >> 3, t = kap & 7;
        float acc[16];
#pragma unroll
        for (int bb = 0; bb < 16; bb++) acc[bb] = 0.f;
#pragma unroll 8
        for (int e = par; e < 64; e += 2) {
            int f = t * 64 + e;
            float w1 = W1[f * 512 + d];
#pragma unroll
            for (int bb = 0; bb < 16; bb++) acc[bb] = fmaf(a[bb][f], w1, acc[bb]);
        }
#pragma unroll
        for (int bb = 0; bb < 16; bb++)
            g_U[(size_t)((b0 + bb) * NKAP + kap) * 512 + d] = acc[bb];
    }
}

// ---------------- K2b: W2^T -> fp16 ----------------
__global__ void k_wconv(const float* __restrict__ W2) {
    __shared__ float t[32][33];
    int k0 = blockIdx.x * 32, n0 = blockIdx.y * 32;
    int tx = threadIdx.x, ty = threadIdx.y;
#pragma unroll
    for (int r = 0; r < 32; r += 8)
        t[ty + r][tx] = W2[(size_t)(k0 + ty + r) * D2 + n0 + tx];
    __syncthreads();
#pragma unroll
    for (int r = 0; r < 32; r += 8) {
        float v = t[tx][ty + r];
        g_Bh[(size_t)(n0 + ty + r) * 512 + k0 + tx] = __float2half_rn(v);
    }
}

// ---------------- K3: fused z computation (no Z1 materialization) -----------
// Block: (s, j-tile of 4) x all 512 d; 256 threads x 2 d each.
// STATS pass accumulates BN1 sums; WRITE pass emits relu(bn1(z)) as fp16 A.
// z arithmetic order matches the old p1->p2 sequence bit-exactly.
#define ZSMEM (188416)   // u 128KB + V 32KB + w 16KB + hw 8KB

template<bool WRITE>
__global__ void __launch_bounds__(256, 1) k_zf(const float* __restrict__ tw) {
    extern __shared__ float sm[];
    float* u   = sm;                       // [4][16][512]
    float* vsh = sm + 4 * 16 * 512;        // [16][512]
    float* wsh = vsh + 16 * 512;           // [64][4][16]
    float* hsh = wsh + 64 * 4 * 16;        // [4][512]
    const int tid = threadIdx.x;
    const int jt = blockIdx.x, s = blockIdx.y;
    const int j0 = jt << 2;
    const int d2 = tid << 1;

    for (int f = tid; f < 8192; f += 256) {            // U_j tile
        int j = f >> 11, r = f & 2047;
        int kap = r >> 7, d4 = (r & 127) << 2;
        *(float4*)&u[(j * 16 + kap) * 512 + d4] =
            *(const float4*)&g_U[(size_t)((((s << 6) + j0 + j) << 4) + kap) * 512 + d4];
    }
    for (int f = tid; f < 2048; f += 256) {            // V
        int kap = f >> 7, d4 = (f & 127) << 2;
        *(float4*)&vsh[kap * 512 + d4] = *(const float4*)&g_V[kap * 512 + d4];
    }
    for (int f = tid; f < 1024; f += 256) {            // w[i][j][kap]
        int i = f >> 4, j = (f >> 2) & 3, kq = (f & 3) << 2;
        *(float4*)&wsh[(i * 4 + j) * 16 + kq] =
            *(const float4*)&tw[(size_t)((s << 12) + (i << 6) + j0 + j) * 16 + kq];
    }
    for (int f = tid; f < 512; f += 256) {             // hW_j tile
        int j = f >> 7, d4 = (f & 127) << 2;
        *(float4*)&hsh[j * 512 + d4] =
            *(const float4*)&g_hW[((s << 6) + j0 + j) * 512 + d4];
    }
    __syncthreads();

    float2 hwr[4];
#pragma unroll
    for (int j = 0; j < 4; j++) hwr[j] = *(float2*)&hsh[j * 512 + d2];
    float2 ab0, ab1v;
    if (WRITE) { ab0 = g_ab1[(s << 9) + d2]; ab1v = g_ab1[(s << 9) + d2 + 1]; }
    float ls0 = 0.f, ls1 = 0.f, lq0 = 0.f, lq1 = 0.f;

#pragma unroll 1
    for (int i = 0; i < 64; i++) {
        float2 vu[16];
#pragma unroll
        for (int kap = 0; kap < 16; kap++) {
            float2 uu = *(const float2*)&g_U[(size_t)((((s << 6) + i) << 4) + kap) * 512 + d2];
            float2 vv = *(float2*)&vsh[kap * 512 + d2];
            vu[kap] = make_float2(vv.x - uu.x, vv.y - uu.y);
        }
        const float* wrow = &wsh[i << 6];
#pragma unroll
        for (int j = 0; j < 4; j++) {
            float a1x = hwr[j].x, a1y = hwr[j].y, a2x = 0.f, a2y = 0.f;
#pragma unroll
            for (int kap = 0; kap < 16; kap++) {
                float wk = wrow[(j << 4) + kap];
                float2 uj = *(float2*)&u[((j << 4) + kap) * 512 + d2];
                a1x = fmaf(wk, uj.x, a1x); a1y = fmaf(wk, uj.y, a1y);
                a2x = fmaf(wk, vu[kap].x, a2x); a2y = fmaf(wk, vu[kap].y, a2y);
            }
            float zx = a1x + a2x, zy = a1y + a2y;
            if (WRITE) {
                float ax = fmaxf(fmaf(ab0.x, zx, ab0.y), 0.f);
                float ay = fmaxf(fmaf(ab1v.x, zy, ab1v.y), 0.f);
                *(__half2*)(g_Ah + (size_t)((s << 12) + (i << 6) + j0 + j) * 512 + d2) =
                    __halves2half2(__float2half_rn(ax), __float2half_rn(ay));
            } else {
                ls0 += zx; ls1 += zy;
                lq0 = fmaf(zx, zx, lq0); lq1 = fmaf(zy, zy, lq1);
            }
        }
    }
    if (!WRITE) {
        atomicAdd(&g_sum1[(s << 9) + d2],     ls0);
        atomicAdd(&g_sum1[(s << 9) + d2 + 1], ls1);
        atomicAdd(&g_sq1 [(s << 9) + d2],     lq0);
        atomicAdd(&g_sq1 [(s << 9) + d2 + 1], lq1);
    }
}

// ---------------- K4: finalize BN1 ----------------
__global__ void k_bn1(const float* __restrict__ g1, const float* __restrict__ be1) {
    int idx = blockIdx.x * 256 + threadIdx.x;
    if (idx >= SQ * 512) return;
    int d = idx & 511;
    const float inv = 1.f / (float)PPRW;
    float m   = g_sum1[idx] * inv;
    float var = g_sq1[idx] * inv - m * m;
    float al  = g1[d] * rsqrtf(var + EPSV);
    g_ab1[idx] = make_float2(al, fmaf(-al, m, be1[d]));
}

// ---------------- K5: HMMA fp16 GEMM2 (single term) -------------------------
#define BK     32
#define APITCH 40
#define TILE_B (128 * APITCH * 2)
#define BUF_B  (2 * TILE_B)
#define GT2_SMEM (2 * BUF_B)

__device__ __forceinline__ void mma16816(float* c, const uint32_t* a, const uint32_t* b) {
    asm volatile("mma.sync.aligned.m16n8k16.row.col.f32.f16.f16.f32 "
                 "{%0,%1,%2,%3}, {%4,%5,%6,%7}, {%8,%9}, {%0,%1,%2,%3};"
                 : "+f"(c[0]), "+f"(c[1]), "+f"(c[2]), "+f"(c[3])
                 : "r"(a[0]), "r"(a[1]), "r"(a[2]), "r"(a[3]), "r"(b[0]), "r"(b[1]));
}
#define LDSM_X4(r, addr) \
    asm volatile("ldmatrix.sync.aligned.m8n8.x4.shared.b16 {%0,%1,%2,%3}, [%4];" \
        : "=r"((r)[0]), "=r"((r)[1]), "=r"((r)[2]), "=r"((r)[3]) : "r"(addr))

__global__ void __launch_bounds__(256, 2) k_gemm2m() {
    extern __shared__ __align__(16) char smem[];
    const uint32_t sb = smem_u32(smem);
    const int tid  = threadIdx.x;
    const int wid  = tid >> 5;
    const int lane = tid & 31;
    const int wy   = wid & 3;
    const int wx   = wid >> 2;
    const int g    = lane >> 2;
    const int t    = lane & 3;
    const int nblk = blockIdx.x;
    const int mblk = blockIdx.y;
    const int n0   = nblk << 7;
    const size_t arow0 = (size_t)mblk << 7;
    const int si0  = mblk << 1;

    const int mrow  = ((lane >> 3) & 1) * 8 + (lane & 7);
    const int kselA = (lane >> 4) << 3;
    const int browB = ((lane >> 4) << 3) + (lane & 7);
    const int kselB = ((lane >> 3) & 1) << 3;
    uint32_t offA[2][2], offB[4][2];
#pragma unroll
    for (int mt = 0; mt < 2; mt++)
#pragma unroll
        for (int ks = 0; ks < 2; ks++)
            offA[mt][ks] = (uint32_t)(((wy * 32 + mt * 16 + mrow) * APITCH + ks * 16 + kselA) * 2);
#pragma unroll
    for (int np = 0; np < 4; np++)
#pragma unroll
        for (int ks = 0; ks < 2; ks++)
            offB[np][ks] = (uint32_t)(((wx * 64 + np * 16 + browB) * APITCH + ks * 16 + kselB) * 2);

    float c[2][8][4];
#pragma unroll
    for (int mt = 0; mt < 2; mt++)
#pragma unroll
        for (int nt = 0; nt < 8; nt++)
#pragma unroll
            for (int r = 0; r < 4; r++) c[mt][nt][r] = 0.f;

#define ISSUE(c_, buf_) do {                                                   \
    int _k0 = (c_) << 5;                                                       \
    char* _bb = smem + (buf_) * BUF_B;                                         \
    _Pragma("unroll")                                                          \
    for (int _q = 0; _q < 4; _q++) {                                           \
        int _seg = tid + (_q << 8);                                            \
        int _tile = _seg >> 9;                                                 \
        int _r = (_seg >> 2) & 127;                                            \
        int _qq = _seg & 3;                                                    \
        const __half* _src = (_tile == 0)                                      \
            ? g_Ah + ((arow0 + _r) << 9) + _k0 + (_qq << 3)                    \
            : g_Bh + ((size_t)(n0 + _r) << 9) + _k0 + (_qq << 3);              \
        uint32_t _dst;                                                         \
        asm("{ .reg .u64 t; cvta.to.shared.u64 t, %1; cvt.u32.u64 %0, t; }"    \
            : "=r"(_dst) : "l"(_bb + _tile * TILE_B + _r * (APITCH * 2) + (_qq << 4))); \
        asm volatile("cp.async.cg.shared.global [%0], [%1], 16;"               \
                     :: "r"(_dst), "l"(_src));                                 \
    }                                                                          \
    asm volatile("cp.async.commit_group;" ::: "memory");                       \
} while (0)

    ISSUE(0, 0);

    for (int ch = 0; ch < 16; ch++) {
        const int buf = ch & 1;
        if (ch < 15) {
            ISSUE(ch + 1, buf ^ 1);
            asm volatile("cp.async.wait_group 1;" ::: "memory");
        } else {
            asm volatile("cp.async.wait_group 0;" ::: "memory");
        }
        __syncthreads();

        const uint32_t tb = sb + buf * BUF_B;
#pragma unroll
        for (int ks = 0; ks < 2; ks++) {
            uint32_t ax[2][4], bx[8][2];
#pragma unroll
            for (int mt = 0; mt < 2; mt++) LDSM_X4(ax[mt], tb + offA[mt][ks]);
#pragma unroll
            for (int np = 0; np < 4; np++) LDSM_X4(&bx[2 * np][0], tb + TILE_B + offB[np][ks]);
#pragma unroll
            for (int nt = 0; nt < 8; nt++)
#pragma unroll
                for (int mt = 0; mt < 2; mt++) mma16816(c[mt][nt], ax[mt], bx[nt]);
        }
        __syncthreads();
    }
#undef ISSUE

    // ---- epilogue: column-wise max/min/sum/sq over this warp's 32 rows ----
    float* s_mx = (float*)smem;            // [8][64]
    float* s_mn = s_mx + 512;
    float* s_sm = s_mn + 512;
    float* s_sq = s_sm + 512;

#pragma unroll
    for (int nt = 0; nt < 8; nt++) {
#pragma unroll
        for (int b = 0; b < 2; b++) {
            float mx = fmaxf(fmaxf(c[0][nt][b], c[0][nt][b + 2]),
                             fmaxf(c[1][nt][b], c[1][nt][b + 2]));
            float mn = fminf(fminf(c[0][nt][b], c[0][nt][b + 2]),
                             fminf(c[1][nt][b], c[1][nt][b + 2]));
            float sm = c[0][nt][b] + c[0][nt][b + 2] + c[1][nt][b] + c[1][nt][b + 2];
            float sq = c[0][nt][b] * c[0][nt][b] + c[0][nt][b + 2] * c[0][nt][b + 2]
                     + c[1][nt][b] * c[1][nt][b] + c[1][nt][b + 2] * c[1][nt][b + 2];
#pragma unroll
            for (int o = 4; o < 32; o <<= 1) {
                mx = fmaxf(mx, __shfl_xor_sync(0xffffffffu, mx, o));
                mn = fminf(mn, __shfl_xor_sync(0xffffffffu, mn, o));
                sm += __shfl_xor_sync(0xffffffffu, sm, o);
                sq += __shfl_xor_sync(0xffffffffu, sq, o);
            }
            if (g == 0) {
                int cl = wid * 64 + (nt << 3) + 2 * t + b;
                s_mx[cl] = mx; s_mn[cl] = mn; s_sm[cl] = sm; s_sq[cl] = sq;
            }
        }
    }
    __syncthreads();

    {
        int jg = tid >> 7, col = tid & 127;
        int wxx = col >> 6, c64 = col & 63;
        int w0 = (wxx << 2) + (jg << 1);
        float mx = fmaxf(s_mx[w0 * 64 + c64], s_mx[(w0 + 1) * 64 + c64]);
        float mn = fminf(s_mn[w0 * 64 + c64], s_mn[(w0 + 1) * 64 + c64]);
        int si = si0 + jg;
        g_maxZ[(size_t)si * D2 + n0 + col] = mx;
        g_minZ[(size_t)si * D2 + n0 + col] = mn;
    }
    if (tid < 128) {
        int col = tid, wxx = col >> 6, c64 = col & 63;
        float sm = 0.f, sq = 0.f;
#pragma unroll
        for (int w = 0; w < 4; w++) {
            sm += s_sm[((wxx << 2) + w) * 64 + c64];
            sq += s_sq[((wxx << 2) + w) * 64 + c64];
        }
        int s_ = si0 >> 6;
        atomicAdd(&g_sum2[s_ * D2 + n0 + col], sm);
        atomicAdd(&g_sq2 [s_ * D2 + n0 + col], sq);
    }
}

// ---------------- K6: finalize BN2 ----------------
__global__ void k_bn2(const float* __restrict__ g2, const float* __restrict__ be2) {
    int idx = blockIdx.x * 256 + threadIdx.x;
    if (idx >= SQ * D2) return;
    int d = idx & (D2 - 1);
    const float inv = 1.f / (float)PPRW;
    float m   = g_sum2[idx] * inv;
    float var = g_sq2[idx] * inv - m * m;
    float al  = g2[d] * rsqrtf(var + EPSV);
    g_ab2[idx] = make_float2(al, fmaf(-al, m, be2[d]));
}

// ---------------- K7: out ----------------
__global__ void k_out(float* __restrict__ out) {
    int idx = blockIdx.x * 256 + threadIdx.x;
    int si = idx >> 10;
    int d  = idx & (D2 - 1);
    int s  = si >> 6;
    float2 abv = g_ab2[s * D2 + d];
    float m = (abv.x >= 0.f) ? g_maxZ[idx] : g_minZ[idx];
    out[idx] = fmaxf(fmaf(abv.x, m, abv.y), 0.f);
}

// ---------------- launch ----------------
extern "C" void kernel_launch(void* const* d_in, const int* in_sizes, int n_in,
                              void* d_out, int out_size) {
    (void)in_sizes; (void)n_in; (void)out_size;
    const float* hs   = (const float*)d_in[0];
    const float* traj = (const float*)d_in[3];
    const float* tw   = (const float*)d_in[4];
    const float* Wsp  = (const float*)d_in[6];
    const float* bsp  = (const float*)d_in[7];
    const float* W1   = (const float*)d_in[8];
    const float* g1   = (const float*)d_in[10];
    const float* be1  = (const float*)d_in[11];
    const float* W2   = (const float*)d_in[12];
    const float* g2   = (const float*)d_in[14];
    const float* be2  = (const float*)d_in[15];
    float* out = (float*)d_out;

    cudaFuncSetAttribute(k_gemm2m, cudaFuncAttributeMaxDynamicSharedMemorySize, GT2_SMEM);
    cudaFuncSetAttribute(k_zf<false>, cudaFuncAttributeMaxDynamicSharedMemorySize, ZSMEM);
    cudaFuncSetAttribute(k_zf<true>,  cudaFuncAttributeMaxDynamicSharedMemorySize, ZSMEM);

    k_zero <<<128, 256>>>();
    k_embed<<<NB, 128>>>(traj, Wsp, hs, W1);
    k_V    <<<4, 128>>>(bsp, W1);
    k_U    <<<dim3(NB / 16, 2), 512>>>(W1);
    k_wconv<<<dim3(16, 32), dim3(32, 8)>>>(W2);
    k_zf<false><<<dim3(16, SQ), 256, ZSMEM>>>(tw);   // BN1 stats, no Z1
    k_bn1  <<<64, 256>>>(g1, be1);
    k_zf<true> <<<dim3(16, SQ), 256, ZSMEM>>>(tw);   // fp16 A, no Z1
    k_gemm2m<<<dim3(8, 1024), 256, GT2_SMEM>>>();
    k_bn2  <<<128, 256>>>(g2, be2);
    k_out  <<<8192, 256>>>(out);
}

// round 15
// speedup vs baseline: 1.0628x; 1.0628x over previous
#include <cuda_runtime.h>
#include <cuda_bf16.h>
#include <cuda_fp16.h>
#include <cstdint>
#include <cstddef>

// ---------------- problem constants ----------------
#define SQ   32
#define PP64 64
#define NB   2048
#define PPRW 4096
#define D1   512
#define D2   1024
#define NKAP 16
#define EPSV 1e-5f

// ---------------- scratch ----------------
__device__ __align__(256) float g_a  [NB * 512];
__device__ __align__(256) float g_hW [NB * 512];
__device__ __align__(256) float g_U  [NB * NKAP * 512];
__device__ __align__(256) float g_V  [NKAP * 512];
__device__ float  g_sum1[SQ * 512];
__device__ float  g_sq1 [SQ * 512];
__device__ float2 g_ab1 [SQ * 512];
__device__ float  g_sum2[SQ * D2];
__device__ float  g_sq2 [SQ * D2];
__device__ float2 g_ab2 [SQ * D2];
__device__ __align__(256) float g_maxZ[NB * D2];
__device__ __align__(256) float g_minZ[NB * D2];
// fp16 operands for HMMA GEMM2
__device__ __align__(256) __half g_Ah[(size_t)NB * PP64 * 512];   // 134 MB
__device__ __align__(256) __half g_Bh[(size_t)D2 * 512];          // W2^T fp16

__device__ __forceinline__ uint32_t smem_u32(const void* p) {
    uint32_t a;
    asm("{ .reg .u64 t; cvta.to.shared.u64 t, %1; cvt.u32.u64 %0, t; }" : "=r"(a) : "l"(p));
    return a;
}

// ---------------- K0: zero BN accumulators ----------------
__global__ void k_zero() {
    int i = blockIdx.x * blockDim.x + threadIdx.x;
    if (i < SQ * 512) { g_sum1[i] = 0.f; g_sq1[i] = 0.f; }
    if (i < SQ * D2)  { g_sum2[i] = 0.f; g_sq2[i] = 0.f; }
}

// ---------------- K1: a = obs @ W_sp ; hW = h @ W1[512:576,:] ----------------
__global__ void k_embed(const float* __restrict__ traj, const float* __restrict__ Wsp,
                        const float* __restrict__ hs,   const float* __restrict__ W1) {
    int b = blockIdx.x;
    int tid = threadIdx.x;
    __shared__ float obs[16];
    __shared__ float hsh[64];
    if (tid < 16) {
        int t = tid >> 1, c = tid & 1;
        obs[tid] = traj[((size_t)t * NB + b) * 2 + c];
    }
    if (tid < 64) hsh[tid] = hs[b * 64 + tid];
    __syncthreads();
#pragma unroll
    for (int q = 0; q < 4; q++) {
        int f = tid + 128 * q;
        float acc = 0.f;
#pragma unroll
        for (int r = 0; r < 16; r++) acc = fmaf(obs[r], Wsp[r * 512 + f], acc);
        g_a[b * 512 + f] = acc;
        float ah = 0.f;
#pragma unroll
        for (int k = 0; k < 64; k++) ah = fmaf(hsh[k], W1[(512 + k) * 512 + f], ah);
        g_hW[b * 512 + f] = ah;
    }
}

// ---------------- K1b: V[kap][d] ----------------
__global__ void k_V(const float* __restrict__ bsp, const float* __restrict__ W1) {
    int d = blockIdx.x * 128 + threadIdx.x;
#pragma unroll
    for (int kap = 0; kap < NKAP; kap++) {
        int par = kap >> 3, t = kap & 7;
        float acc = 0.f;
#pragma unroll 4
        for (int e = par; e < 64; e += 2) {
            int f = t * 64 + e;
            acc = fmaf(bsp[f], W1[f * 512 + d], acc);
        }
        g_V[kap * 512 + d] = acc;
    }
}

// ---------------- K2: U[b][kap][d]; 16 peds/block, kappa split x2 ----------------
__global__ void k_U(const float* __restrict__ W1) {
    int b0 = blockIdx.x * 16;
    int kap0 = blockIdx.y * 8;
    int d  = threadIdx.x;
    __shared__ float a[16][512];
    for (int idx = threadIdx.x; idx < 16 * 512; idx += 512)
        a[idx >> 9][idx & 511] = g_a[b0 * 512 + idx];
    __syncthreads();
#pragma unroll 1
    for (int kk = 0; kk < 8; kk++) {
        int kap = kap0 + kk;
        int par = kap >> 3, t = kap & 7;
        float acc[16];
#pragma unroll
        for (int bb = 0; bb < 16; bb++) acc[bb] = 0.f;
#pragma unroll 8
        for (int e = par; e < 64; e += 2) {
            int f = t * 64 + e;
            float w1 = W1[f * 512 + d];
#pragma unroll
            for (int bb = 0; bb < 16; bb++) acc[bb] = fmaf(a[bb][f], w1, acc[bb]);
        }
#pragma unroll
        for (int bb = 0; bb < 16; bb++)
            g_U[(size_t)((b0 + bb) * NKAP + kap) * 512 + d] = acc[bb];
    }
}

// ---------------- K2b: W2^T -> fp16 ----------------
__global__ void k_wconv(const float* __restrict__ W2) {
    __shared__ float t[32][33];
    int k0 = blockIdx.x * 32, n0 = blockIdx.y * 32;
    int tx = threadIdx.x, ty = threadIdx.y;
#pragma unroll
    for (int r = 0; r < 32; r += 8)
        t[ty + r][tx] = W2[(size_t)(k0 + ty + r) * D2 + n0 + tx];
    __syncthreads();
#pragma unroll
    for (int r = 0; r < 32; r += 8) {
        float v = t[tx][ty + r];
        g_Bh[(size_t)(n0 + ty + r) * 512 + k0 + tx] = __float2half_rn(v);
    }
}

// ---------------- K3: fused z computation (no Z1), prefetched U_i -----------
// Block: (s, j-tile of 4) x all 512 d; 256 threads x 2 d each.
// STATS pass accumulates BN1 sums; WRITE pass emits relu(bn1(z)) as fp16 A.
// z arithmetic order matches the original p1->p2 sequence bit-exactly.
#define ZSMEM (188416)   // u 128KB + V 32KB + w 16KB + hw 8KB

template<bool WRITE>
__global__ void __launch_bounds__(256, 1) k_zf(const float* __restrict__ tw) {
    extern __shared__ float sm[];
    float* u   = sm;                       // [4][16][512]
    float* vsh = sm + 4 * 16 * 512;        // [16][512]
    float* wsh = vsh + 16 * 512;           // [64][4][16]
    float* hsh = wsh + 64 * 4 * 16;        // [4][512]
    const int tid = threadIdx.x;
    const int jt = blockIdx.x, s = blockIdx.y;
    const int j0 = jt << 2;
    const int d2 = tid << 1;

    for (int f = tid; f < 8192; f += 256) {            // U_j tile
        int j = f >> 11, r = f & 2047;
        int kap = r >> 7, d4 = (r & 127) << 2;
        *(float4*)&u[(j * 16 + kap) * 512 + d4] =
            *(const float4*)&g_U[(size_t)((((s << 6) + j0 + j) << 4) + kap) * 512 + d4];
    }
    for (int f = tid; f < 2048; f += 256) {            // V
        int kap = f >> 7, d4 = (f & 127) << 2;
        *(float4*)&vsh[kap * 512 + d4] = *(const float4*)&g_V[kap * 512 + d4];
    }
    for (int f = tid; f < 1024; f += 256) {            // w[i][j][kap]
        int i = f >> 4, j = (f >> 2) & 3, kq = (f & 3) << 2;
        *(float4*)&wsh[(i * 4 + j) * 16 + kq] =
            *(const float4*)&tw[(size_t)((s << 12) + (i << 6) + j0 + j) * 16 + kq];
    }
    for (int f = tid; f < 512; f += 256) {             // hW_j tile
        int j = f >> 7, d4 = (f & 127) << 2;
        *(float4*)&hsh[j * 512 + d4] =
            *(const float4*)&g_hW[((s << 6) + j0 + j) * 512 + d4];
    }
    __syncthreads();

    float2 hwr[4];
#pragma unroll
    for (int j = 0; j < 4; j++) hwr[j] = *(float2*)&hsh[j * 512 + d2];
    float2 vr[16];                                      // V slice, register-resident
#pragma unroll
    for (int kap = 0; kap < 16; kap++) vr[kap] = *(float2*)&vsh[kap * 512 + d2];
    float2 ab0, ab1v;
    if (WRITE) { ab0 = g_ab1[(s << 9) + d2]; ab1v = g_ab1[(s << 9) + d2 + 1]; }
    float ls0 = 0.f, ls1 = 0.f, lq0 = 0.f, lq1 = 0.f;

    // prefetch U_i for i = 0
    float2 uu[16];
#pragma unroll
    for (int kap = 0; kap < 16; kap++)
        uu[kap] = *(const float2*)&g_U[(size_t)(((s << 6) << 4) + kap) * 512 + d2];

#pragma unroll 1
    for (int i = 0; i < 64; i++) {
        float2 vu[16];
#pragma unroll
        for (int kap = 0; kap < 16; kap++)
            vu[kap] = make_float2(vr[kap].x - uu[kap].x, vr[kap].y - uu[kap].y);
        if (i < 63) {                                   // prefetch U_{i+1}
#pragma unroll
            for (int kap = 0; kap < 16; kap++)
                uu[kap] = *(const float2*)&g_U[(size_t)((((s << 6) + i + 1) << 4) + kap) * 512 + d2];
        }
        const float* wrow = &wsh[i << 6];
#pragma unroll
        for (int j = 0; j < 4; j++) {
            float a1x = hwr[j].x, a1y = hwr[j].y, a2x = 0.f, a2y = 0.f;
#pragma unroll
            for (int kap = 0; kap < 16; kap++) {
                float wk = wrow[(j << 4) + kap];
                float2 uj = *(float2*)&u[((j << 4) + kap) * 512 + d2];
                a1x = fmaf(wk, uj.x, a1x); a1y = fmaf(wk, uj.y, a1y);
                a2x = fmaf(wk, vu[kap].x, a2x); a2y = fmaf(wk, vu[kap].y, a2y);
            }
            float zx = a1x + a2x, zy = a1y + a2y;
            if (WRITE) {
                float ax = fmaxf(fmaf(ab0.x, zx, ab0.y), 0.f);
                float ay = fmaxf(fmaf(ab1v.x, zy, ab1v.y), 0.f);
                *(__half2*)(g_Ah + (size_t)((s << 12) + (i << 6) + j0 + j) * 512 + d2) =
                    __halves2half2(__float2half_rn(ax), __float2half_rn(ay));
            } else {
                ls0 += zx; ls1 += zy;
                lq0 = fmaf(zx, zx, lq0); lq1 = fmaf(zy, zy, lq1);
            }
        }
    }
    if (!WRITE) {
        atomicAdd(&g_sum1[(s << 9) + d2],     ls0);
        atomicAdd(&g_sum1[(s << 9) + d2 + 1], ls1);
        atomicAdd(&g_sq1 [(s << 9) + d2],     lq0);
        atomicAdd(&g_sq1 [(s << 9) + d2 + 1], lq1);
    }
}

// ---------------- K4: finalize BN1 ----------------
__global__ void k_bn1(const float* __restrict__ g1, const float* __restrict__ be1) {
    int idx = blockIdx.x * 256 + threadIdx.x;
    if (idx >= SQ * 512) return;
    int d = idx & 511;
    const float inv = 1.f / (float)PPRW;
    float m   = g_sum1[idx] * inv;
    float var = g_sq1[idx] * inv - m * m;
    float al  = g1[d] * rsqrtf(var + EPSV);
    g_ab1[idx] = make_float2(al, fmaf(-al, m, be1[d]));
}

// ---------------- K5: HMMA fp16 GEMM2 (single term) -------------------------
#define BK     32
#define APITCH 40
#define TILE_B (128 * APITCH * 2)
#define BUF_B  (2 * TILE_B)
#define GT2_SMEM (2 * BUF_B)

__device__ __forceinline__ void mma16816(float* c, const uint32_t* a, const uint32_t* b) {
    asm volatile("mma.sync.aligned.m16n8k16.row.col.f32.f16.f16.f32 "
                 "{%0,%1,%2,%3}, {%4,%5,%6,%7}, {%8,%9}, {%0,%1,%2,%3};"
                 : "+f"(c[0]), "+f"(c[1]), "+f"(c[2]), "+f"(c[3])
                 : "r"(a[0]), "r"(a[1]), "r"(a[2]), "r"(a[3]), "r"(b[0]), "r"(b[1]));
}
#define LDSM_X4(r, addr) \
    asm volatile("ldmatrix.sync.aligned.m8n8.x4.shared.b16 {%0,%1,%2,%3}, [%4];" \
        : "=r"((r)[0]), "=r"((r)[1]), "=r"((r)[2]), "=r"((r)[3]) : "r"(addr))

__global__ void __launch_bounds__(256, 2) k_gemm2m() {
    extern __shared__ __align__(16) char smem[];
    const uint32_t sb = smem_u32(smem);
    const int tid  = threadIdx.x;
    const int wid  = tid >> 5;
    const int lane = tid & 31;
    const int wy   = wid & 3;
    const int wx   = wid >> 2;
    const int g    = lane >> 2;
    const int t    = lane & 3;
    const int nblk = blockIdx.x;
    const int mblk = blockIdx.y;
    const int n0   = nblk << 7;
    const size_t arow0 = (size_t)mblk << 7;
    const int si0  = mblk << 1;

    const int mrow  = ((lane >> 3) & 1) * 8 + (lane & 7);
    const int kselA = (lane >> 4) << 3;
    const int browB = ((lane >> 4) << 3) + (lane & 7);
    const int kselB = ((lane >> 3) & 1) << 3;
    uint32_t offA[2][2], offB[4][2];
#pragma unroll
    for (int mt = 0; mt < 2; mt++)
#pragma unroll
        for (int ks = 0; ks < 2; ks++)
            offA[mt][ks] = (uint32_t)(((wy * 32 + mt * 16 + mrow) * APITCH + ks * 16 + kselA) * 2);
#pragma unroll
    for (int np = 0; np < 4; np++)
#pragma unroll
        for (int ks = 0; ks < 2; ks++)
            offB[np][ks] = (uint32_t)(((wx * 64 + np * 16 + browB) * APITCH + ks * 16 + kselB) * 2);

    float c[2][8][4];
#pragma unroll
    for (int mt = 0; mt < 2; mt++)
#pragma unroll
        for (int nt = 0; nt < 8; nt++)
#pragma unroll
            for (int r = 0; r < 4; r++) c[mt][nt][r] = 0.f;

#define ISSUE(c_, buf_) do {                                                   \
    int _k0 = (c_) << 5;                                                       \
    char* _bb = smem + (buf_) * BUF_B;                                         \
    _Pragma("unroll")                                                          \
    for (int _q = 0; _q < 4; _q++) {                                           \
        int _seg = tid + (_q << 8);                                            \
        int _tile = _seg >> 9;                                                 \
        int _r = (_seg >> 2) & 127;                                            \
        int _qq = _seg & 3;                                                    \
        const __half* _src = (_tile == 0)                                      \
            ? g_Ah + ((arow0 + _r) << 9) + _k0 + (_qq << 3)                    \
            : g_Bh + ((size_t)(n0 + _r) << 9) + _k0 + (_qq << 3);              \
        uint32_t _dst;                                                         \
        asm("{ .reg .u64 t; cvta.to.shared.u64 t, %1; cvt.u32.u64 %0, t; }"    \
            : "=r"(_dst) : "l"(_bb + _tile * TILE_B + _r * (APITCH * 2) + (_qq << 4))); \
        asm volatile("cp.async.cg.shared.global [%0], [%1], 16;"               \
                     :: "r"(_dst), "l"(_src));                                 \
    }                                                                          \
    asm volatile("cp.async.commit_group;" ::: "memory");                       \
} while (0)

    ISSUE(0, 0);

    for (int ch = 0; ch < 16; ch++) {
        const int buf = ch & 1;
        if (ch < 15) {
            ISSUE(ch + 1, buf ^ 1);
            asm volatile("cp.async.wait_group 1;" ::: "memory");
        } else {
            asm volatile("cp.async.wait_group 0;" ::: "memory");
        }
        __syncthreads();

        const uint32_t tb = sb + buf * BUF_B;
#pragma unroll
        for (int ks = 0; ks < 2; ks++) {
            uint32_t ax[2][4], bx[8][2];
#pragma unroll
            for (int mt = 0; mt < 2; mt++) LDSM_X4(ax[mt], tb + offA[mt][ks]);
#pragma unroll
            for (int np = 0; np < 4; np++) LDSM_X4(&bx[2 * np][0], tb + TILE_B + offB[np][ks]);
#pragma unroll
            for (int nt = 0; nt < 8; nt++)
#pragma unroll
                for (int mt = 0; mt < 2; mt++) mma16816(c[mt][nt], ax[mt], bx[nt]);
        }
        __syncthreads();
    }
#undef ISSUE

    // ---- epilogue: column-wise max/min/sum/sq over this warp's 32 rows ----
    float* s_mx = (float*)smem;            // [8][64]
    float* s_mn = s_mx + 512;
    float* s_sm = s_mn + 512;
    float* s_sq = s_sm + 512;

#pragma unroll
    for (int nt = 0; nt < 8; nt++) {
#pragma unroll
        for (int b = 0; b < 2; b++) {
            float mx = fmaxf(fmaxf(c[0][nt][b], c[0][nt][b + 2]),
                             fmaxf(c[1][nt][b], c[1][nt][b + 2]));
            float mn = fminf(fminf(c[0][nt][b], c[0][nt][b + 2]),
                             fminf(c[1][nt][b], c[1][nt][b + 2]));
            float sm = c[0][nt][b] + c[0][nt][b + 2] + c[1][nt][b] + c[1][nt][b + 2];
            float sq = c[0][nt][b] * c[0][nt][b] + c[0][nt][b + 2] * c[0][nt][b + 2]
                     + c[1][nt][b] * c[1][nt][b] + c[1][nt][b + 2] * c[1][nt][b + 2];
#pragma unroll
            for (int o = 4; o < 32; o <<= 1) {
                mx = fmaxf(mx, __shfl_xor_sync(0xffffffffu, mx, o));
                mn = fminf(mn, __shfl_xor_sync(0xffffffffu, mn, o));
                sm += __shfl_xor_sync(0xffffffffu, sm, o);
                sq += __shfl_xor_sync(0xffffffffu, sq, o);
            }
            if (g == 0) {
                int cl = wid * 64 + (nt << 3) + 2 * t + b;
                s_mx[cl] = mx; s_mn[cl] = mn; s_sm[cl] = sm; s_sq[cl] = sq;
            }
        }
    }
    __syncthreads();

    {
        int jg = tid >> 7, col = tid & 127;
        int wxx = col >> 6, c64 = col & 63;
        int w0 = (wxx << 2) + (jg << 1);
        float mx = fmaxf(s_mx[w0 * 64 + c64], s_mx[(w0 + 1) * 64 + c64]);
        float mn = fminf(s_mn[w0 * 64 + c64], s_mn[(w0 + 1) * 64 + c64]);
        int si = si0 + jg;
        g_maxZ[(size_t)si * D2 + n0 + col] = mx;
        g_minZ[(size_t)si * D2 + n0 + col] = mn;
    }
    if (tid < 128) {
        int col = tid, wxx = col >> 6, c64 = col & 63;
        float sm = 0.f, sq = 0.f;
#pragma unroll
        for (int w = 0; w < 4; w++) {
            sm += s_sm[((wxx << 2) + w) * 64 + c64];
            sq += s_sq[((wxx << 2) + w) * 64 + c64];
        }
        int s_ = si0 >> 6;
        atomicAdd(&g_sum2[s_ * D2 + n0 + col], sm);
        atomicAdd(&g_sq2 [s_ * D2 + n0 + col], sq);
    }
}

// ---------------- K6: finalize BN2 ----------------
__global__ void k_bn2(const float* __restrict__ g2, const float* __restrict__ be2) {
    int idx = blockIdx.x * 256 + threadIdx.x;
    if (idx >= SQ * D2) return;
    int d = idx & (D2 - 1);
    const float inv = 1.f / (float)PPRW;
    float m   = g_sum2[idx] * inv;
    float var = g_sq2[idx] * inv - m * m;
    float al  = g2[d] * rsqrtf(var + EPSV);
    g_ab2[idx] = make_float2(al, fmaf(-al, m, be2[d]));
}

// ---------------- K7: out ----------------
__global__ void k_out(float* __restrict__ out) {
    int idx = blockIdx.x * 256 + threadIdx.x;
    int si = idx >> 10;
    int d  = idx & (D2 - 1);
    int s  = si >> 6;
    float2 abv = g_ab2[s * D2 + d];
    float m = (abv.x >= 0.f) ? g_maxZ[idx] : g_minZ[idx];
    out[idx] = fmaxf(fmaf(abv.x, m, abv.y), 0.f);
}

// ---------------- launch ----------------
extern "C" void kernel_launch(void* const* d_in, const int* in_sizes, int n_in,
                              void* d_out, int out_size) {
    (void)in_sizes; (void)n_in; (void)out_size;
    const float* hs   = (const float*)d_in[0];
    const float* traj = (const float*)d_in[3];
    const float* tw   = (const float*)d_in[4];
    const float* Wsp  = (const float*)d_in[6];
    const float* bsp  = (const float*)d_in[7];
    const float* W1   = (const float*)d_in[8];
    const float* g1   = (const float*)d_in[10];
    const float* be1  = (const float*)d_in[11];
    const float* W2   = (const float*)d_in[12];
    const float* g2   = (const float*)d_in[14];
    const float* be2  = (const float*)d_in[15];
    float* out = (float*)d_out;

    cudaFuncSetAttribute(k_gemm2m, cudaFuncAttributeMaxDynamicSharedMemorySize, GT2_SMEM);
    cudaFuncSetAttribute(k_zf<false>, cudaFuncAttributeMaxDynamicSharedMemorySize, ZSMEM);
    cudaFuncSetAttribute(k_zf<true>,  cudaFuncAttributeMaxDynamicSharedMemorySize, ZSMEM);

    k_zero <<<128, 256>>>();
    k_embed<<<NB, 128>>>(traj, Wsp, hs, W1);
    k_V    <<<4, 128>>>(bsp, W1);
    k_U    <<<dim3(NB / 16, 2), 512>>>(W1);
    k_wconv<<<dim3(16, 32), dim3(32, 8)>>>(W2);
    k_zf<false><<<dim3(16, SQ), 256, ZSMEM>>>(tw);   // BN1 stats, no Z1
    k_bn1  <<<64, 256>>>(g1, be1);
    k_zf<true> <<<dim3(16, SQ), 256, ZSMEM>>>(tw);   // fp16 A, no Z1
    k_gemm2m<<<dim3(8, 1024), 256, GT2_SMEM>>>();
    k_bn2  <<<128, 256>>>(g2, be2);
    k_out  <<<8192, 256>>>(out);
}

// round 16
// speedup vs baseline: 1.1213x; 1.0550x over previous
#include <cuda_runtime.h>
#include <cuda_bf16.h>
#include <cuda_fp16.h>
#include <cstdint>
#include <cstddef>

// ---------------- problem constants ----------------
#define SQ   32
#define PP64 64
#define NB   2048
#define PPRW 4096
#define D1   512
#define D2   1024
#define NKAP 16
#define EPSV 1e-5f

// ---------------- scratch ----------------
__device__ __align__(256) float g_a  [NB * 512];
__device__ __align__(256) float g_hW [NB * 512];
__device__ __align__(256) float g_U  [NB * NKAP * 512];
__device__ __align__(256) float g_V  [NKAP * 512];
__device__ __align__(256) __half g_Z1h[(size_t)NB * PP64 * 512];  // fp16 Z1 (134 MB)
__device__ float  g_sum1[SQ * 512];
__device__ float  g_sq1 [SQ * 512];
__device__ float2 g_ab1 [SQ * 512];
__device__ float  g_sum2[SQ * D2];
__device__ float  g_sq2 [SQ * D2];
__device__ float2 g_ab2 [SQ * D2];
__device__ __align__(256) float g_maxZ[NB * D2];
__device__ __align__(256) float g_minZ[NB * D2];
// fp16 operands for HMMA GEMM2
__device__ __align__(256) __half g_Ah[(size_t)NB * PP64 * 512];   // 134 MB
__device__ __align__(256) __half g_Bh[(size_t)D2 * 512];          // W2^T fp16

__device__ __forceinline__ uint32_t smem_u32(const void* p) {
    uint32_t a;
    asm("{ .reg .u64 t; cvta.to.shared.u64 t, %1; cvt.u32.u64 %0, t; }" : "=r"(a) : "l"(p));
    return a;
}

// ---------------- K0: zero BN accumulators ----------------
__global__ void k_zero() {
    int i = blockIdx.x * blockDim.x + threadIdx.x;
    if (i < SQ * 512) { g_sum1[i] = 0.f; g_sq1[i] = 0.f; }
    if (i < SQ * D2)  { g_sum2[i] = 0.f; g_sq2[i] = 0.f; }
}

// ---------------- K1: a = obs @ W_sp ; hW = h @ W1[512:576,:] ----------------
__global__ void k_embed(const float* __restrict__ traj, const float* __restrict__ Wsp,
                        const float* __restrict__ hs,   const float* __restrict__ W1) {
    int b = blockIdx.x;
    int tid = threadIdx.x;
    __shared__ float obs[16];
    __shared__ float hsh[64];
    if (tid < 16) {
        int t = tid >> 1, c = tid & 1;
        obs[tid] = traj[((size_t)t * NB + b) * 2 + c];
    }
    if (tid < 64) hsh[tid] = hs[b * 64 + tid];
    __syncthreads();
#pragma unroll
    for (int q = 0; q < 4; q++) {
        int f = tid + 128 * q;
        float acc = 0.f;
#pragma unroll
        for (int r = 0; r < 16; r++) acc = fmaf(obs[r], Wsp[r * 512 + f], acc);
        g_a[b * 512 + f] = acc;
        float ah = 0.f;
#pragma unroll
        for (int k = 0; k < 64; k++) ah = fmaf(hsh[k], W1[(512 + k) * 512 + f], ah);
        g_hW[b * 512 + f] = ah;
    }
}

// ---------------- K1b: V[kap][d] ----------------
__global__ void k_V(const float* __restrict__ bsp, const float* __restrict__ W1) {
    int d = blockIdx.x * 128 + threadIdx.x;
#pragma unroll
    for (int kap = 0; kap < NKAP; kap++) {
        int par = kap >> 3, t = kap & 7;
        float acc = 0.f;
#pragma unroll 4
        for (int e = par; e < 64; e += 2) {
            int f = t * 64 + e;
            acc = fmaf(bsp[f], W1[f * 512 + d], acc);
        }
        g_V[kap * 512 + d] = acc;
    }
}

// ---------------- K2: U[b][kap][d]; 16 peds/block, kappa split x2 ----------------
__global__ void k_U(const float* __restrict__ W1) {
    int b0 = blockIdx.x * 16;
    int kap0 = blockIdx.y * 8;
    int d  = threadIdx.x;
    __shared__ float a[16][512];
    for (int idx = threadIdx.x; idx < 16 * 512; idx += 512)
        a[idx >> 9][idx & 511] = g_a[b0 * 512 + idx];
    __syncthreads();
#pragma unroll 1
    for (int kk = 0; kk < 8; kk++) {
        int kap = kap0 + kk;
        int par = kap >> 3, t = kap & 7;
        float acc[16];
#pragma unroll
        for (int bb = 0; bb < 16; bb++) acc[bb] = 0.f;
#pragma unroll 8
        for (int e = par; e < 64; e += 2) {
            int f = t * 64 + e;
            float w1 = W1[f * 512 + d];
#pragma unroll
            for (int bb = 0; bb < 16; bb++) acc[bb] = fmaf(a[bb][f], w1, acc[bb]);
        }
#pragma unroll
        for (int bb = 0; bb < 16; bb++)
            g_U[(size_t)((b0 + bb) * NKAP + kap) * 512 + d] = acc[bb];
    }
}

// ---------------- K2b: W2^T -> fp16 ----------------
__global__ void k_wconv(const float* __restrict__ W2) {
    __shared__ float t[32][33];
    int k0 = blockIdx.x * 32, n0 = blockIdx.y * 32;
    int tx = threadIdx.x, ty = threadIdx.y;
#pragma unroll
    for (int r = 0; r < 32; r += 8)
        t[ty + r][tx] = W2[(size_t)(k0 + ty + r) * D2 + n0 + tx];
    __syncthreads();
#pragma unroll
    for (int r = 0; r < 32; r += 8) {
        float v = t[tx][ty + r];
        g_Bh[(size_t)(n0 + ty + r) * 512 + k0 + tx] = __float2half_rn(v);
    }
}

// ---------------- K3a: Z1h[(i,j)][d] = fp16(hW_j + sum w*U_j); 2 d/thread ----
__global__ void k_p1(const float* __restrict__ tw) {
    int tid = threadIdx.x;
    int dt = blockIdx.x, j = blockIdx.y, s = blockIdx.z;   // dt in {0,1}
    int d  = (dt << 8) + (tid << 1);
    int bj = (s << 6) + j;
    __shared__ float wsh[64][16];
    for (int idx = tid; idx < 1024; idx += 128) {
        int i = idx >> 4, kap = idx & 15;
        wsh[i][kap] = tw[(size_t)((s << 12) + (i << 6) + j) * 16 + kap];
    }
    float2 uj[16];
#pragma unroll
    for (int kap = 0; kap < 16; kap++)
        uj[kap] = *(const float2*)&g_U[(size_t)((bj << 4) + kap) * 512 + d];
    float2 hwj = *(const float2*)&g_hW[bj * 512 + d];
    __syncthreads();
    __half2* zbase = (__half2*)(g_Z1h + (size_t)((s << 12) + j) * 512 + d);
#pragma unroll 4
    for (int i = 0; i < 64; i++) {
        float ax = hwj.x, ay = hwj.y;
#pragma unroll
        for (int kap = 0; kap < 16; kap++) {
            float wk = wsh[i][kap];
            ax = fmaf(wk, uj[kap].x, ax);
            ay = fmaf(wk, uj[kap].y, ay);
        }
        zbase[(size_t)i * 16384] = __floats2half2_rn(ax, ay);   // i stride: 64*512 halves
    }
}

// ---------------- K3b: Z1h += w*(V-U_i); BN1 stats (fp32 regs) --------------
__global__ void k_p2(const float* __restrict__ tw) {
    int tid = threadIdx.x;
    int dt = blockIdx.x, i = blockIdx.y, s = blockIdx.z;   // dt in {0,1}
    int d  = (dt << 8) + (tid << 1);
    int bi = (s << 6) + i;
    __shared__ float wsh[64][16];
    for (int idx = tid; idx < 1024; idx += 128)
        ((float*)wsh)[idx] = tw[(size_t)((s << 12) + (i << 6)) * 16 + idx];
    float2 vu[16];
#pragma unroll
    for (int kap = 0; kap < 16; kap++) {
        float2 uu = *(const float2*)&g_U[(size_t)((bi << 4) + kap) * 512 + d];
        float2 vv = *(const float2*)&g_V[(kap << 9) + d];
        vu[kap] = make_float2(vv.x - uu.x, vv.y - uu.y);
    }
    __syncthreads();
    float ls0 = 0.f, ls1 = 0.f, lq0 = 0.f, lq1 = 0.f;
    __half2* zbase = (__half2*)(g_Z1h + (size_t)((s << 12) + (i << 6)) * 512 + d);
#pragma unroll 4
    for (int j = 0; j < 64; j++) {
        float ax = 0.f, ay = 0.f;
#pragma unroll
        for (int kap = 0; kap < 16; kap++) {
            float wk = wsh[j][kap];
            ax = fmaf(wk, vu[kap].x, ax);
            ay = fmaf(wk, vu[kap].y, ay);
        }
        float2 zo = __half22float2(zbase[(size_t)j * 256]);    // j stride: 512 halves
        float zx = zo.x + ax, zy = zo.y + ay;
        zbase[(size_t)j * 256] = __floats2half2_rn(zx, zy);
        ls0 += zx; ls1 += zy;
        lq0 = fmaf(zx, zx, lq0); lq1 = fmaf(zy, zy, lq1);
    }
    atomicAdd(&g_sum1[(s << 9) + d],     ls0);
    atomicAdd(&g_sum1[(s << 9) + d + 1], ls1);
    atomicAdd(&g_sq1 [(s << 9) + d],     lq0);
    atomicAdd(&g_sq1 [(s << 9) + d + 1], lq1);
}

// ---------------- K4: finalize BN1 ----------------
__global__ void k_bn1(const float* __restrict__ g1, const float* __restrict__ be1) {
    int idx = blockIdx.x * 256 + threadIdx.x;
    if (idx >= SQ * 512) return;
    int d = idx & 511;
    const float inv = 1.f / (float)PPRW;
    float m   = g_sum1[idx] * inv;
    float var = g_sq1[idx] * inv - m * m;
    float al  = g1[d] * rsqrtf(var + EPSV);
    g_ab1[idx] = make_float2(al, fmaf(-al, m, be1[d]));
}

// ---------------- K4b: A1 = relu(bn1(Z1h)) -> fp16; 8 elems/thread ----------
__global__ void k_conv() {
    size_t idx = ((size_t)blockIdx.x * 256 + threadIdx.x) * 8;   // grid 32768
    uint4 zp = *(const uint4*)(g_Z1h + idx);
    const __half2* z2 = (const __half2*)&zp;
    int d = (int)(idx & 511);
    int s = (int)(idx >> 21);
    const float2* abp = g_ab1 + (s << 9) + d;
    uint4 op;
    __half2* o2 = (__half2*)&op;
#pragma unroll
    for (int q = 0; q < 4; q++) {
        float2 zz = __half22float2(z2[q]);
        float2 aL = abp[2 * q], aH = abp[2 * q + 1];
        float ax = fmaxf(fmaf(aL.x, zz.x, aL.y), 0.f);
        float ay = fmaxf(fmaf(aH.x, zz.y, aH.y), 0.f);
        o2[q] = __floats2half2_rn(ax, ay);
    }
    *(uint4*)(g_Ah + idx) = op;
}

// ---------------- K5: HMMA fp16 GEMM2 (single term) -------------------------
#define BK     32
#define APITCH 40
#define TILE_B (128 * APITCH * 2)
#define BUF_B  (2 * TILE_B)
#define GT2_SMEM (2 * BUF_B)

__device__ __forceinline__ void mma16816(float* c, const uint32_t* a, const uint32_t* b) {
    asm volatile("mma.sync.aligned.m16n8k16.row.col.f32.f16.f16.f32 "
                 "{%0,%1,%2,%3}, {%4,%5,%6,%7}, {%8,%9}, {%0,%1,%2,%3};"
                 : "+f"(c[0]), "+f"(c[1]), "+f"(c[2]), "+f"(c[3])
                 : "r"(a[0]), "r"(a[1]), "r"(a[2]), "r"(a[3]), "r"(b[0]), "r"(b[1]));
}
#define LDSM_X4(r, addr) \
    asm volatile("ldmatrix.sync.aligned.m8n8.x4.shared.b16 {%0,%1,%2,%3}, [%4];" \
        : "=r"((r)[0]), "=r"((r)[1]), "=r"((r)[2]), "=r"((r)[3]) : "r"(addr))

__global__ void __launch_bounds__(256, 2) k_gemm2m() {
    extern __shared__ __align__(16) char smem[];
    const uint32_t sb = smem_u32(smem);
    const int tid  = threadIdx.x;
    const int wid  = tid >> 5;
    const int lane = tid & 31;
    const int wy   = wid & 3;
    const int wx   = wid >> 2;
    const int g    = lane >> 2;
    const int t    = lane & 3;
    const int nblk = blockIdx.x;
    const int mblk = blockIdx.y;
    const int n0   = nblk << 7;
    const size_t arow0 = (size_t)mblk << 7;
    const int si0  = mblk << 1;

    const int mrow  = ((lane >> 3) & 1) * 8 + (lane & 7);
    const int kselA = (lane >> 4) << 3;
    const int browB = ((lane >> 4) << 3) + (lane & 7);
    const int kselB = ((lane >> 3) & 1) << 3;
    uint32_t offA[2][2], offB[4][2];
#pragma unroll
    for (int mt = 0; mt < 2; mt++)
#pragma unroll
        for (int ks = 0; ks < 2; ks++)
            offA[mt][ks] = (uint32_t)(((wy * 32 + mt * 16 + mrow) * APITCH + ks * 16 + kselA) * 2);
#pragma unroll
    for (int np = 0; np < 4; np++)
#pragma unroll
        for (int ks = 0; ks < 2; ks++)
            offB[np][ks] = (uint32_t)(((wx * 64 + np * 16 + browB) * APITCH + ks * 16 + kselB) * 2);

    float c[2][8][4];
#pragma unroll
    for (int mt = 0; mt < 2; mt++)
#pragma unroll
        for (int nt = 0; nt < 8; nt++)
#pragma unroll
            for (int r = 0; r < 4; r++) c[mt][nt][r] = 0.f;

#define ISSUE(c_, buf_) do {                                                   \
    int _k0 = (c_) << 5;                                                       \
    char* _bb = smem + (buf_) * BUF_B;                                         \
    _Pragma("unroll")                                                          \
    for (int _q = 0; _q < 4; _q++) {                                           \
        int _seg = tid + (_q << 8);                                            \
        int _tile = _seg >> 9;                                                 \
        int _r = (_seg >> 2) & 127;                                            \
        int _qq = _seg & 3;                                                    \
        const __half* _src = (_tile == 0)                                      \
            ? g_Ah + ((arow0 + _r) << 9) + _k0 + (_qq << 3)                    \
            : g_Bh + ((size_t)(n0 + _r) << 9) + _k0 + (_qq << 3);              \
        uint32_t _dst;                                                         \
        asm("{ .reg .u64 t; cvta.to.shared.u64 t, %1; cvt.u32.u64 %0, t; }"    \
            : "=r"(_dst) : "l"(_bb + _tile * TILE_B + _r * (APITCH * 2) + (_qq << 4))); \
        asm volatile("cp.async.cg.shared.global [%0], [%1], 16;"               \
                     :: "r"(_dst), "l"(_src));                                 \
    }                                                                          \
    asm volatile("cp.async.commit_group;" ::: "memory");                       \
} while (0)

    ISSUE(0, 0);

    for (int ch = 0; ch < 16; ch++) {
        const int buf = ch & 1;
        if (ch < 15) {
            ISSUE(ch + 1, buf ^ 1);
            asm volatile("cp.async.wait_group 1;" ::: "memory");
        } else {
            asm volatile("cp.async.wait_group 0;" ::: "memory");
        }
        __syncthreads();

        const uint32_t tb = sb + buf * BUF_B;
#pragma unroll
        for (int ks = 0; ks < 2; ks++) {
            uint32_t ax[2][4], bx[8][2];
#pragma unroll
            for (int mt = 0; mt < 2; mt++) LDSM_X4(ax[mt], tb + offA[mt][ks]);
#pragma unroll
            for (int np = 0; np < 4; np++) LDSM_X4(&bx[2 * np][0], tb + TILE_B + offB[np][ks]);
#pragma unroll
            for (int nt = 0; nt < 8; nt++)
#pragma unroll
                for (int mt = 0; mt < 2; mt++) mma16816(c[mt][nt], ax[mt], bx[nt]);
        }
        __syncthreads();
    }
#undef ISSUE

    // ---- epilogue: column-wise max/min/sum/sq over this warp's 32 rows ----
    float* s_mx = (float*)smem;            // [8][64]
    float* s_mn = s_mx + 512;
    float* s_sm = s_mn + 512;
    float* s_sq = s_sm + 512;

#pragma unroll
    for (int nt = 0; nt < 8; nt++) {
#pragma unroll
        for (int b = 0; b < 2; b++) {
            float mx = fmaxf(fmaxf(c[0][nt][b], c[0][nt][b + 2]),
                             fmaxf(c[1][nt][b], c[1][nt][b + 2]));
            float mn = fminf(fminf(c[0][nt][b], c[0][nt][b + 2]),
                             fminf(c[1][nt][b], c[1][nt][b + 2]));
            float sm = c[0][nt][b] + c[0][nt][b + 2] + c[1][nt][b] + c[1][nt][b + 2];
            float sq = c[0][nt][b] * c[0][nt][b] + c[0][nt][b + 2] * c[0][nt][b + 2]
                     + c[1][nt][b] * c[1][nt][b] + c[1][nt][b + 2] * c[1][nt][b + 2];
#pragma unroll
            for (int o = 4; o < 32; o <<= 1) {
                mx = fmaxf(mx, __shfl_xor_sync(0xffffffffu, mx, o));
                mn = fminf(mn, __shfl_xor_sync(0xffffffffu, mn, o));
                sm += __shfl_xor_sync(0xffffffffu, sm, o);
                sq += __shfl_xor_sync(0xffffffffu, sq, o);
            }
            if (g == 0) {
                int cl = wid * 64 + (nt << 3) + 2 * t + b;
                s_mx[cl] = mx; s_mn[cl] = mn; s_sm[cl] = sm; s_sq[cl] = sq;
            }
        }
    }
    __syncthreads();

    {
        int jg = tid >> 7, col = tid & 127;
        int wxx = col >> 6, c64 = col & 63;
        int w0 = (wxx << 2) + (jg << 1);
        float mx = fmaxf(s_mx[w0 * 64 + c64], s_mx[(w0 + 1) * 64 + c64]);
        float mn = fminf(s_mn[w0 * 64 + c64], s_mn[(w0 + 1) * 64 + c64]);
        int si = si0 + jg;
        g_maxZ[(size_t)si * D2 + n0 + col] = mx;
        g_minZ[(size_t)si * D2 + n0 + col] = mn;
    }
    if (tid < 128) {
        int col = tid, wxx = col >> 6, c64 = col & 63;
        float sm = 0.f, sq = 0.f;
#pragma unroll
        for (int w = 0; w < 4; w++) {
            sm += s_sm[((wxx << 2) + w) * 64 + c64];
            sq += s_sq[((wxx << 2) + w) * 64 + c64];
        }
        int s_ = si0 >> 6;
        atomicAdd(&g_sum2[s_ * D2 + n0 + col], sm);
        atomicAdd(&g_sq2 [s_ * D2 + n0 + col], sq);
    }
}

// ---------------- K6: finalize BN2 ----------------
__global__ void k_bn2(const float* __restrict__ g2, const float* __restrict__ be2) {
    int idx = blockIdx.x * 256 + threadIdx.x;
    if (idx >= SQ * D2) return;
    int d = idx & (D2 - 1);
    const float inv = 1.f / (float)PPRW;
    float m   = g_sum2[idx] * inv;
    float var = g_sq2[idx] * inv - m * m;
    float al  = g2[d] * rsqrtf(var + EPSV);
    g_ab2[idx] = make_float2(al, fmaf(-al, m, be2[d]));
}

// ---------------- K7: out ----------------
__global__ void k_out(float* __restrict__ out) {
    int idx = blockIdx.x * 256 + threadIdx.x;
    int si = idx >> 10;
    int d  = idx & (D2 - 1);
    int s  = si >> 6;
    float2 abv = g_ab2[s * D2 + d];
    float m = (abv.x >= 0.f) ? g_maxZ[idx] : g_minZ[idx];
    out[idx] = fmaxf(fmaf(abv.x, m, abv.y), 0.f);
}

// ---------------- launch ----------------
extern "C" void kernel_launch(void* const* d_in, const int* in_sizes, int n_in,
                              void* d_out, int out_size) {
    (void)in_sizes; (void)n_in; (void)out_size;
    const float* hs   = (const float*)d_in[0];
    const float* traj = (const float*)d_in[3];
    const float* tw   = (const float*)d_in[4];
    const float* Wsp  = (const float*)d_in[6];
    const float* bsp  = (const float*)d_in[7];
    const float* W1   = (const float*)d_in[8];
    const float* g1   = (const float*)d_in[10];
    const float* be1  = (const float*)d_in[11];
    const float* W2   = (const float*)d_in[12];
    const float* g2   = (const float*)d_in[14];
    const float* be2  = (const float*)d_in[15];
    float* out = (float*)d_out;

    cudaFuncSetAttribute(k_gemm2m, cudaFuncAttributeMaxDynamicSharedMemorySize, GT2_SMEM);

    k_zero <<<128, 256>>>();
    k_embed<<<NB, 128>>>(traj, Wsp, hs, W1);
    k_V    <<<4, 128>>>(bsp, W1);
    k_U    <<<dim3(NB / 16, 2), 512>>>(W1);
    k_wconv<<<dim3(16, 32), dim3(32, 8)>>>(W2);
    k_p1   <<<dim3(2, 64, SQ), 128>>>(tw);
    k_p2   <<<dim3(2, 64, SQ), 128>>>(tw);
    k_bn1  <<<64, 256>>>(g1, be1);
    k_conv <<<32768, 256>>>();
    k_gemm2m<<<dim3(8, 1024), 256, GT2_SMEM>>>();
    k_bn2  <<<128, 256>>>(g2, be2);
    k_out  <<<8192, 256>>>(out);
}